// round 6
// baseline (speedup 1.0000x reference)
#include <cuda_runtime.h>
#include <cstdint>

#define B_    128
#define T_    512
#define D_    256
#define H_    1024
#define G4_   4096
#define Z_    128
#define NBLK  128      // one block per 8 h-columns (1024/8)
#define NTHR  256
#define HPAD  33       // padded row stride for Hs/Gs (bank-conflict-free)

// Persistent state (allocation-free scratch): double-buffered h, grid barrier.
__device__ float        g_h[2][B_ * H_];
__device__ unsigned int g_bar;

// ---------------------------------------------------------------------------
// Reset kernel: zero h buffer 0 and the barrier counter (runs each launch so
// graph replays are deterministic).
// ---------------------------------------------------------------------------
__global__ void reset_kernel() {
    int i = blockIdx.x * blockDim.x + threadIdx.x;
    if (i == 0) g_bar = 0u;
    for (int e = i; e < B_ * H_; e += gridDim.x * blockDim.x)
        g_h[0][e] = 0.0f;
}

__device__ __forceinline__ float sigmoid_f(float x) {
    return 1.0f / (1.0f + expf(-x));
}
__device__ __forceinline__ float softplus_f(float x) {
    // log1p(exp(x)) stable form
    return fmaxf(x, 0.0f) + log1pf(expf(-fabsf(x)));
}

// ---------------------------------------------------------------------------
// Persistent LSTM kernel.
// Block n owns h-columns [8n, 8n+8) -> gate columns {g*1024 + 8n + jj}.
// Per step: gates[128,32] = [h | x_t] @ [U ; W] + b  (K = 1024 + 256 = 1280),
// then elementwise cell update; c stays in registers; h double-buffered global.
// ---------------------------------------------------------------------------
__global__ void __launch_bounds__(NTHR, 1)
lstm_kernel(const float* __restrict__ x,   // [B, T, D]
            const float* __restrict__ W,   // [D, 4H]
            const float* __restrict__ U,   // [H, 4H]
            const float* __restrict__ bias)// [4H]
{
    __shared__ float Hs[B_ * HPAD];   // h/x tile [128][33]; reused as Gs after K-loop
    __shared__ float Us[32 * 32];     // U/W tile [kk][cc], k-major

    const int tid = threadIdx.x;
    const int j0  = blockIdx.x * 8;   // first owned h column
    const int tx  = tid & 7;          // col group (8 groups of 4 cols)
    const int ry  = tid >> 3;         // row group (32 groups of 4 rows)
    const int r0  = ry * 4;
    const int c0  = tx * 4;

    // Bias for this thread's 4 gate columns (constant across steps).
    float breg[4];
#pragma unroll
    for (int cn = 0; cn < 4; cn++) {
        int cc = c0 + cn;                       // local col 0..31
        breg[cn] = bias[(cc >> 3) * H_ + j0 + (cc & 7)];
    }

    // Cell state: element e = 4*tid+q, e = row*8 + jj.
    float creg[4] = {0.f, 0.f, 0.f, 0.f};

    for (int t = 0; t < T_; t++) {
        const float* hread  = g_h[t & 1];
        float*       hwrite = g_h[(t + 1) & 1];

        float acc[4][4];
#pragma unroll
        for (int r = 0; r < 4; r++)
#pragma unroll
            for (int c = 0; c < 4; c++) acc[r][c] = 0.0f;

        // K loop: chunks 0..31 -> h@U (K=1024); chunks 32..39 -> x_t@W (K=256)
        for (int ch = 0; ch < 40; ch++) {
            __syncthreads();   // Hs/Us reuse guard
            if (ch < 32) {
                const int k0 = ch * 32;
                // Stage Hs[row][kk] = h[row][k0+kk]  (ldcg: bypass stale L1)
#pragma unroll
                for (int q = 0; q < 4; q++) {
                    int i   = tid + NTHR * q;
                    int row = i >> 3, cs = i & 7;
                    float4 v = __ldcg((const float4*)(hread + row * H_ + k0 + 4 * cs));
                    float* d = &Hs[row * HPAD + 4 * cs];
                    d[0] = v.x; d[1] = v.y; d[2] = v.z; d[3] = v.w;
                }
                // Stage Us[kk][cc] = U[k0+kk][gate*1024 + j0 + jj]
                {
                    int kk = tid >> 3, gs = (tid >> 1) & 3, hf = tid & 1;
                    float4 u = __ldg((const float4*)(U + (size_t)(k0 + kk) * G4_ +
                                                     gs * H_ + j0 + hf * 4));
                    float* d = &Us[kk * 32 + gs * 8 + hf * 4];
                    d[0] = u.x; d[1] = u.y; d[2] = u.z; d[3] = u.w;
                }
            } else {
                const int kx0 = (ch - 32) * 32;
                // Stage Hs[row][kk] = x[row, t, kx0+kk]
#pragma unroll
                for (int q = 0; q < 4; q++) {
                    int i   = tid + NTHR * q;
                    int row = i >> 3, cs = i & 7;
                    float4 v = __ldg((const float4*)(x + ((size_t)row * T_ + t) * D_ +
                                                     kx0 + 4 * cs));
                    float* d = &Hs[row * HPAD + 4 * cs];
                    d[0] = v.x; d[1] = v.y; d[2] = v.z; d[3] = v.w;
                }
                {
                    int kk = tid >> 3, gs = (tid >> 1) & 3, hf = tid & 1;
                    float4 u = __ldg((const float4*)(W + (size_t)(kx0 + kk) * G4_ +
                                                     gs * H_ + j0 + hf * 4));
                    float* d = &Us[kk * 32 + gs * 8 + hf * 4];
                    d[0] = u.x; d[1] = u.y; d[2] = u.z; d[3] = u.w;
                }
            }
            __syncthreads();

            // Compute: 4x4 register tile over this 32-wide K chunk.
#pragma unroll 8
            for (int kk = 0; kk < 32; kk++) {
                float4 u = *(const float4*)&Us[kk * 32 + c0];
                float h0 = Hs[(r0 + 0) * HPAD + kk];
                float h1 = Hs[(r0 + 1) * HPAD + kk];
                float h2 = Hs[(r0 + 2) * HPAD + kk];
                float h3 = Hs[(r0 + 3) * HPAD + kk];
                acc[0][0] += h0 * u.x; acc[0][1] += h0 * u.y;
                acc[0][2] += h0 * u.z; acc[0][3] += h0 * u.w;
                acc[1][0] += h1 * u.x; acc[1][1] += h1 * u.y;
                acc[1][2] += h1 * u.z; acc[1][3] += h1 * u.w;
                acc[2][0] += h2 * u.x; acc[2][1] += h2 * u.y;
                acc[2][2] += h2 * u.z; acc[2][3] += h2 * u.w;
                acc[3][0] += h3 * u.x; acc[3][1] += h3 * u.y;
                acc[3][2] += h3 * u.z; acc[3][3] += h3 * u.w;
            }
        }

        // Exchange gates through smem (reuse Hs as Gs) for the i/f/g/o combine.
        __syncthreads();
#pragma unroll
        for (int r = 0; r < 4; r++)
#pragma unroll
            for (int c = 0; c < 4; c++)
                Hs[(r0 + r) * HPAD + c0 + c] = acc[r][c] + breg[c];
        __syncthreads();

        // Cell update for this block's 128x8 h slice (4 elements / thread).
#pragma unroll
        for (int q = 0; q < 4; q++) {
            int e   = tid * 4 + q;
            int row = e >> 3, jj = e & 7;
            float gi = Hs[row * HPAD + 0  + jj];
            float gf = Hs[row * HPAD + 8  + jj];
            float gg = Hs[row * HPAD + 16 + jj];
            float go = Hs[row * HPAD + 24 + jj];
            float iv = sigmoid_f(gi);
            float fv = sigmoid_f(gf);
            float ov = sigmoid_f(go);
            float gv = softplus_f(gg);
            float cn = fv * creg[q] + iv * gv;
            creg[q] = cn;
            float hn = ov * softplus_f(cn);
            __stcg(hwrite + row * H_ + j0 + jj, hn);
        }

        // Grid barrier (single wave: 128 blocks <= 148 SMs).
        __syncthreads();
        if (tid == 0) {
            __threadfence();
            atomicAdd(&g_bar, 1u);
            const unsigned int target = (unsigned int)(t + 1) * (unsigned int)gridDim.x;
            while (*(volatile unsigned int*)&g_bar < target) { __nanosleep(64); }
            __threadfence();
        }
        __syncthreads();
    }
}

// ---------------------------------------------------------------------------
// Final projections: mu = h@Wm + bm; logvar = h@Wv + bv; z = mu + eps*exp(lv/2).
// h_last lives in g_h[0] (t=511 writes buffer (511+1)&1 = 0).
// Output layout: [mu (B*Z) | logvar (B*Z) | z (B*Z)].
// ---------------------------------------------------------------------------
__global__ void __launch_bounds__(Z_)
proj_kernel(const float* __restrict__ Wm, const float* __restrict__ bm,
            const float* __restrict__ Wv, const float* __restrict__ bv,
            const float* __restrict__ eps, float* __restrict__ out)
{
    __shared__ float hs[H_];
    const int b = blockIdx.x;
    const int z = threadIdx.x;
    const float* hrow = g_h[0] + (size_t)b * H_;
    for (int k = z; k < H_; k += Z_) hs[k] = hrow[k];
    __syncthreads();

    float am = bm[z];
    float av = bv[z];
#pragma unroll 4
    for (int k = 0; k < H_; k++) {
        float hk = hs[k];
        am += hk * Wm[(size_t)k * Z_ + z];
        av += hk * Wv[(size_t)k * Z_ + z];
    }
    float zz = am + eps[(size_t)b * Z_ + z] * expf(0.5f * av);
    out[(size_t)b * Z_ + z]                 = am;
    out[(size_t)(B_ * Z_) + b * Z_ + z]     = av;
    out[(size_t)(2 * B_ * Z_) + b * Z_ + z] = zz;
}

// ---------------------------------------------------------------------------
extern "C" void kernel_launch(void* const* d_in, const int* in_sizes, int n_in,
                              void* d_out, int out_size)
{
    const float* x   = (const float*)d_in[0];
    const float* W   = (const float*)d_in[1];
    const float* U   = (const float*)d_in[2];
    const float* b   = (const float*)d_in[3];
    const float* Wm  = (const float*)d_in[4];
    const float* bm  = (const float*)d_in[5];
    const float* Wv  = (const float*)d_in[6];
    const float* bv  = (const float*)d_in[7];
    const float* eps = (const float*)d_in[8];
    float* out = (float*)d_out;

    reset_kernel<<<256, 256>>>();
    lstm_kernel<<<NBLK, NTHR>>>(x, W, U, b);
    proj_kernel<<<B_, Z_>>>(Wm, bm, Wv, bv, eps, out);
}

// round 7
// speedup vs baseline: 1.1153x; 1.1153x over previous
#include <cuda_runtime.h>
#include <cstdint>

#define B_    128
#define T_    512
#define D_    256
#define H_    1024
#define G4_   4096
#define Z_    128
#define NBLK  128      // one block per 8 h-columns (1024/8)
#define NTHR  256
#define SH    36       // Hs row stride (floats): 32 k + 4 pad, 16B-aligned rows
#define SU    36       // Us_t col stride (floats)
#define NCH   40       // 8 x-chunks (K=256) + 32 h-chunks (K=1024)

typedef unsigned long long ull;

// Persistent state: double-buffered h, grid barrier.
__device__ float        g_h[2][B_ * H_];
__device__ unsigned int g_bar;

__global__ void reset_kernel() {
    int i = blockIdx.x * blockDim.x + threadIdx.x;
    if (i == 0) g_bar = 0u;
    for (int e = i; e < B_ * H_; e += gridDim.x * blockDim.x)
        g_h[0][e] = 0.0f;
}

__device__ __forceinline__ float sigmoid_f(float x) {
    return 1.0f / (1.0f + expf(-x));
}
__device__ __forceinline__ float softplus_f(float x) {
    return fmaxf(x, 0.0f) + log1pf(expf(-fabsf(x)));
}
__device__ __forceinline__ void ffma2(ull& d, ull a, ull b) {
    asm("fma.rn.f32x2 %0, %1, %2, %0;" : "+l"(d) : "l"(a), "l"(b));
}
__device__ __forceinline__ float lane_lo(ull v) {
    return __uint_as_float((unsigned)(v & 0xffffffffu));
}
__device__ __forceinline__ float lane_hi(ull v) {
    return __uint_as_float((unsigned)(v >> 32));
}

// ---------------------------------------------------------------------------
// Persistent LSTM kernel. Block n owns h-columns [8n, 8n+8).
// Thread (ry, tx): rows {ry, ry+32, ry+64, ry+96}, local cols {tx, tx+8,
// tx+16, tx+24} = gates i/f/g/o of h-column j0+tx -> gate combine is
// register-local, no smem exchange.
// Accumulators are f32x2 packed over K parity (even-k lane, odd-k lane).
// ---------------------------------------------------------------------------
__global__ void __launch_bounds__(NTHR, 1)
lstm_kernel(const float* __restrict__ x,   // [B, T, D]
            const float* __restrict__ W,   // [D, 4H]
            const float* __restrict__ U,   // [H, 4H]
            const float* __restrict__ bias)// [4H]
{
    __shared__ __align__(16) float HsA[2][B_ * SH];   // [row][k] row-major
    __shared__ __align__(16) float UsA[2][32 * SU];   // [local col][k] (transposed)

    const int tid = threadIdx.x;
    const int j0  = blockIdx.x * 8;
    const int tx  = tid & 7;
    const int ry  = tid >> 3;          // 0..31

    // staging indices
    const int s_row = tid >> 3;        // 0..31 (plus 32q)
    const int s_cs  = tid & 7;
    const int u_kk  = tid >> 3;        // 0..31
    const int u_c   = (tid & 7) * 4;   // 0,4,..,28
    const int u_gcol = (u_c >> 3) * H_ + j0 + (u_c & 7);   // global col of U/W

    float breg[4];
#pragma unroll
    for (int cn = 0; cn < 4; cn++) breg[cn] = bias[cn * H_ + j0 + tx];

    float creg[4] = {0.f, 0.f, 0.f, 0.f};

    for (int t = 0; t < T_; t++) {
        const float* hread  = g_h[t & 1];
        float*       hwrite = g_h[(t + 1) & 1];

        ull acc[4][4];
#pragma unroll
        for (int r = 0; r < 4; r++)
#pragma unroll
            for (int c = 0; c < 4; c++) acc[r][c] = 0ull;

        float4 hx[4];  // staged H/X fragment
        float4 uw;     // staged U/W fragment

        // ---- stage chunk 0 (x chunk) ----
#pragma unroll
        for (int q = 0; q < 4; q++) {
            int row = s_row + 32 * q;
            hx[q] = __ldg((const float4*)(x + ((size_t)row * T_ + t) * D_ + 4 * s_cs));
        }
        uw = __ldg((const float4*)(W + (size_t)u_kk * G4_ + u_gcol));
#pragma unroll
        for (int q = 0; q < 4; q++) {
            int row = s_row + 32 * q;
            *(float4*)&HsA[0][row * SH + 4 * s_cs] = hx[q];
        }
        UsA[0][(u_c + 0) * SU + u_kk] = uw.x;
        UsA[0][(u_c + 1) * SU + u_kk] = uw.y;
        UsA[0][(u_c + 2) * SU + u_kk] = uw.z;
        UsA[0][(u_c + 3) * SU + u_kk] = uw.w;
        __syncthreads();

        for (int ch = 0; ch < NCH; ch++) {
            const int cur = ch & 1;

            // ---- issue global loads for chunk ch+1 (latency hides under compute)
            if (ch + 1 < NCH) {
                if (ch + 1 < 8) {            // x chunk: k = 32*(ch+1)
                    const int k0x = (ch + 1) * 32;
#pragma unroll
                    for (int q = 0; q < 4; q++) {
                        int row = s_row + 32 * q;
                        hx[q] = __ldg((const float4*)(x + ((size_t)row * T_ + t) * D_ +
                                                      k0x + 4 * s_cs));
                    }
                    uw = __ldg((const float4*)(W + (size_t)(k0x + u_kk) * G4_ + u_gcol));
                } else {                      // h chunk: k = 32*(ch+1-8)
                    const int k0 = (ch + 1 - 8) * 32;
#pragma unroll
                    for (int q = 0; q < 4; q++) {
                        int row = s_row + 32 * q;
                        hx[q] = __ldcg((const float4*)(hread + (size_t)row * H_ +
                                                       k0 + 4 * s_cs));
                    }
                    uw = __ldg((const float4*)(U + (size_t)(k0 + u_kk) * G4_ + u_gcol));
                }
            }

            // ---- compute over this 32-k chunk (f32x2, K-parity packed) ----
            {
                const float* Hb = HsA[cur];
                const float* Ub = UsA[cur];
#pragma unroll
                for (int kq = 0; kq < 8; kq++) {          // 4 k per kq
                    ulonglong2 hv[4], uv[4];
#pragma unroll
                    for (int r = 0; r < 4; r++)
                        hv[r] = *(const ulonglong2*)(Hb + (ry + 32 * r) * SH + 4 * kq);
#pragma unroll
                    for (int cn = 0; cn < 4; cn++)
                        uv[cn] = *(const ulonglong2*)(Ub + (tx + 8 * cn) * SU + 4 * kq);
#pragma unroll
                    for (int r = 0; r < 4; r++)
#pragma unroll
                        for (int cn = 0; cn < 4; cn++) {
                            ffma2(acc[r][cn], hv[r].x, uv[cn].x);
                            ffma2(acc[r][cn], hv[r].y, uv[cn].y);
                        }
                }
            }

            // ---- store staged chunk ch+1 into the other buffer ----
            if (ch + 1 < NCH) {
                const int nxt = cur ^ 1;
#pragma unroll
                for (int q = 0; q < 4; q++) {
                    int row = s_row + 32 * q;
                    *(float4*)&HsA[nxt][row * SH + 4 * s_cs] = hx[q];
                }
                UsA[nxt][(u_c + 0) * SU + u_kk] = uw.x;
                UsA[nxt][(u_c + 1) * SU + u_kk] = uw.y;
                UsA[nxt][(u_c + 2) * SU + u_kk] = uw.z;
                UsA[nxt][(u_c + 3) * SU + u_kk] = uw.w;
            }
            __syncthreads();
        }

        // ---- cell update: all 4 gates of (row, j0+tx) live in this thread ----
#pragma unroll
        for (int r = 0; r < 4; r++) {
            float gi = lane_lo(acc[r][0]) + lane_hi(acc[r][0]) + breg[0];
            float gf = lane_lo(acc[r][1]) + lane_hi(acc[r][1]) + breg[1];
            float gg = lane_lo(acc[r][2]) + lane_hi(acc[r][2]) + breg[2];
            float go = lane_lo(acc[r][3]) + lane_hi(acc[r][3]) + breg[3];
            float iv = sigmoid_f(gi);
            float fv = sigmoid_f(gf);
            float ov = sigmoid_f(go);
            float gv = softplus_f(gg);
            float cn = fv * creg[r] + iv * gv;
            creg[r] = cn;
            float hn = ov * softplus_f(cn);
            int row = ry + 32 * r;
            __stcg(hwrite + (size_t)row * H_ + j0 + tx, hn);
        }

        // ---- grid barrier (single wave: 128 blocks <= 148 SMs) ----
        __syncthreads();
        if (tid == 0) {
            __threadfence();
            atomicAdd(&g_bar, 1u);
            const unsigned int target = (unsigned int)(t + 1) * (unsigned int)gridDim.x;
            while (*(volatile unsigned int*)&g_bar < target) { __nanosleep(64); }
            __threadfence();
        }
        __syncthreads();
    }
}

// ---------------------------------------------------------------------------
// Final projections. h_last is in g_h[0] (t=511 writes buffer (511+1)&1 = 0).
// Output: [mu (B*Z) | logvar (B*Z) | z (B*Z)].
// ---------------------------------------------------------------------------
__global__ void __launch_bounds__(Z_)
proj_kernel(const float* __restrict__ Wm, const float* __restrict__ bm,
            const float* __restrict__ Wv, const float* __restrict__ bv,
            const float* __restrict__ eps, float* __restrict__ out)
{
    __shared__ float hs[H_];
    const int b = blockIdx.x;
    const int z = threadIdx.x;
    const float* hrow = g_h[0] + (size_t)b * H_;
    for (int k = z; k < H_; k += Z_) hs[k] = hrow[k];
    __syncthreads();

    float am = bm[z];
    float av = bv[z];
#pragma unroll 4
    for (int k = 0; k < H_; k++) {
        float hk = hs[k];
        am += hk * Wm[(size_t)k * Z_ + z];
        av += hk * Wv[(size_t)k * Z_ + z];
    }
    float zz = am + eps[(size_t)b * Z_ + z] * expf(0.5f * av);
    out[(size_t)b * Z_ + z]                 = am;
    out[(size_t)(B_ * Z_) + b * Z_ + z]     = av;
    out[(size_t)(2 * B_ * Z_) + b * Z_ + z] = zz;
}

// ---------------------------------------------------------------------------
extern "C" void kernel_launch(void* const* d_in, const int* in_sizes, int n_in,
                              void* d_out, int out_size)
{
    const float* x   = (const float*)d_in[0];
    const float* W   = (const float*)d_in[1];
    const float* U   = (const float*)d_in[2];
    const float* b   = (const float*)d_in[3];
    const float* Wm  = (const float*)d_in[4];
    const float* bm  = (const float*)d_in[5];
    const float* Wv  = (const float*)d_in[6];
    const float* bv  = (const float*)d_in[7];
    const float* eps = (const float*)d_in[8];
    float* out = (float*)d_out;

    reset_kernel<<<256, 256>>>();
    lstm_kernel<<<NBLK, NTHR>>>(x, W, U, b);
    proj_kernel<<<B_, Z_>>>(Wm, bm, Wv, bv, eps, out);
}